// round 4
// baseline (speedup 1.0000x reference)
#include <cuda_runtime.h>

#define DDIM 64
#define KCODES 1024
#define BM 64
#define BK 128
#define TM 4
#define TN 8
#define NTHREADS 256
#define HW 4096
#define NTOT (32*64*64)   /* 131072 rows */

__device__ float  g_ek2[KCODES];
__device__ double g_loss;

__global__ void zero_loss_kernel() { g_loss = 0.0; }

__global__ void ek2_kernel(const float* __restrict__ emb) {
    int k = blockIdx.x * blockDim.x + threadIdx.x;
    if (k >= KCODES) return;
    const float4* e4 = (const float4*)(emb + (size_t)k * DDIM);
    float s = 0.f;
#pragma unroll
    for (int i = 0; i < DDIM / 4; i++) {
        float4 v = e4[i];
        s += v.x * v.x + v.y * v.y + v.z * v.z + v.w * v.w;
    }
    g_ek2[k] = s;
}

__global__ __launch_bounds__(NTHREADS)
void vq_kernel(const float* __restrict__ z, const float* __restrict__ emb,
               float* __restrict__ out) {
    __shared__ float zs[DDIM][BM];    // z tile, [d][i]        16 KB
    __shared__ float es[DDIM][BK];    // emb chunk, [d][k]     32 KB
    __shared__ float rv[BM][16];      // per-row min vals       4 KB
    __shared__ int   ri[BM][16];      // per-row min idx        4 KB
    __shared__ int   idx_s[BM];
    __shared__ float wsum[8];

    const int tid = threadIdx.x;
    const int tx = tid & 15;    // code dimension (16 lanes x TN=8 -> 128 codes)
    const int ty = tid >> 4;    // row  dimension (16 lanes x TM=4 -> 64 rows)

    const int nbase = blockIdx.x * BM;
    const int b   = nbase >> 12;       // / 4096
    const int hw0 = nbase & (HW - 1);

    // ---- load z tile: z[b, d, hw0 + i] -> zs[d][i] (coalesced, no transpose) ----
    const float* zb = z + (size_t)b * DDIM * HW + hw0;
#pragma unroll
    for (int it = 0; it < 4; it++) {
        int i4 = it * NTHREADS + tid;          // 1024 float4 total
        int d  = i4 >> 4;
        int c4 = i4 & 15;
        float4 v = *(const float4*)(zb + (size_t)d * HW + c4 * 4);
        *(float4*)(&zs[d][c4 * 4]) = v;
    }

    float mv[TM];
    int   mi[TM];
#pragma unroll
    for (int r = 0; r < TM; r++) { mv[r] = 3.4e38f; mi[r] = 0; }

    for (int kc = 0; kc < KCODES / BK; kc++) {
        const int k0 = kc * BK;
        __syncthreads();   // protect es reuse (also covers zs on first iter)

        // ---- load emb chunk with transpose: emb[k0+k][d] -> es[d][k] ----
        {
            int k     = tid >> 1;
            int dbase = (tid & 1) * 32;
            const float4* er = (const float4*)(emb + (size_t)(k0 + k) * DDIM + dbase);
#pragma unroll
            for (int i = 0; i < 8; i++) {
                float4 v = er[i];
                int d = dbase + i * 4;
                es[d + 0][k] = v.x;
                es[d + 1][k] = v.y;
                es[d + 2][k] = v.z;
                es[d + 3][k] = v.w;
            }
        }
        __syncthreads();

        float acc[TM][TN];
#pragma unroll
        for (int r = 0; r < TM; r++)
#pragma unroll
            for (int c = 0; c < TN; c++) acc[r][c] = 0.f;

#pragma unroll 8
        for (int d = 0; d < DDIM; d++) {
            float4 a  = *(const float4*)(&zs[d][ty * 4]);
            float4 b0 = *(const float4*)(&es[d][tx * 8]);
            float4 b1 = *(const float4*)(&es[d][tx * 8 + 4]);
            float av[TM] = {a.x, a.y, a.z, a.w};
            float bv[TN] = {b0.x, b0.y, b0.z, b0.w, b1.x, b1.y, b1.z, b1.w};
#pragma unroll
            for (int r = 0; r < TM; r++)
#pragma unroll
                for (int c = 0; c < TN; c++)
                    acc[r][c] += av[r] * bv[c];
        }

        // ---- running min update: s = ||e||^2 - 2*dot ----
        float4 q0 = *(const float4*)(&g_ek2[k0 + tx * 8]);
        float4 q1 = *(const float4*)(&g_ek2[k0 + tx * 8 + 4]);
        float qv[TN] = {q0.x, q0.y, q0.z, q0.w, q1.x, q1.y, q1.z, q1.w};
#pragma unroll
        for (int r = 0; r < TM; r++)
#pragma unroll
            for (int c = 0; c < TN; c++) {
                float s = qv[c] - 2.f * acc[r][c];
                if (s < mv[r]) { mv[r] = s; mi[r] = k0 + tx * 8 + c; }
            }
    }

    // ---- cross-thread argmin reduction (first-occurrence tie rule) ----
    __syncthreads();
#pragma unroll
    for (int r = 0; r < TM; r++) {
        rv[ty * 4 + r][tx] = mv[r];
        ri[ty * 4 + r][tx] = mi[r];
    }
    __syncthreads();
    if (tid < BM) {
        float best = rv[tid][0];
        int   bi   = ri[tid][0];
#pragma unroll
        for (int j = 1; j < 16; j++) {
            float v  = rv[tid][j];
            int   ii = ri[tid][j];
            if (v < best || (v == best && ii < bi)) { best = v; bi = ii; }
        }
        idx_s[tid] = bi;
    }
    __syncthreads();

    // ---- epilogue: gather codebook rows, transposed coalesced store, loss ----
    float* outb = out + (size_t)b * DDIM * HW + hw0;
    float lsum = 0.f;
#pragma unroll
    for (int it = 0; it < 16; it++) {
        int e = it * NTHREADS + tid;   // 4096 elements
        int d = e >> 6;
        int i = e & 63;
        float q = __ldg(&emb[(size_t)idx_s[i] * DDIM + d]);
        outb[(size_t)d * HW + i] = q;
        float diff = q - zs[d][i];
        lsum += diff * diff;
    }
    // block reduce loss
#pragma unroll
    for (int o = 16; o > 0; o >>= 1)
        lsum += __shfl_xor_sync(0xffffffffu, lsum, o);
    if ((tid & 31) == 0) wsum[tid >> 5] = lsum;
    __syncthreads();
    if (tid == 0) {
        float t = 0.f;
#pragma unroll
        for (int j = 0; j < 8; j++) t += wsum[j];
        atomicAdd(&g_loss, (double)t);
    }
}

__global__ void finalize_kernel(float* out, int loss_idx) {
    out[loss_idx] = (float)(g_loss * (1.25 / 8388608.0));
}

extern "C" void kernel_launch(void* const* d_in, const int* in_sizes, int n_in,
                              void* d_out, int out_size) {
    const float* z   = (const float*)d_in[0];
    const float* emb = (const float*)d_in[1];
    float* out = (float*)d_out;

    zero_loss_kernel<<<1, 1>>>();
    ek2_kernel<<<KCODES / 128, 128>>>(emb);
    vq_kernel<<<NTOT / BM, NTHREADS>>>(z, emb, out);
    finalize_kernel<<<1, 1>>>(out, out_size - 1);
}